// round 7
// baseline (speedup 1.0000x reference)
#include <cuda_runtime.h>
#include <cuda_bf16.h>
#include <cuda_fp16.h>
#include <cstdint>

#define NMAX 20000
#define EMAX 320000
#define F 64
#define H 4

// ------------------- scratch (static device globals; no allocation) -------------------
// fp16 projections, interleaved layout: halves at  n*256 + p*8 + h*2 + k
// (p = g-pair index 0..31, k = element within pair, h = head)
// -> one 16-byte chunk per (n,p) holds all 4 heads of that g-pair.
__device__ __half  g_Rh[NMAX * H * F];
__device__ __half  g_Th[NMAX * H * F];
__device__ float   g_srad[NMAX * H];      // [n][h]
__device__ float   g_stan[NMAX * H];
__device__ float   g_agg[NMAX * F];       // head-averaged aggregate
__device__ float   g_vrad[H * F];         // w_proj @ radial_score
__device__ float   g_vtan[H * F];

// CSR sort scratch
__device__ int     g_cnt[NMAX];
__device__ int     g_off[NMAX + 1];
__device__ int     g_cur[NMAX];
__device__ int     g_ss[EMAX];            // sorted sender
__device__ float   g_sl[EMAX];            // sorted edge_len
__device__ float4  g_er[EMAX];            // exp(rad logit - max) per head
__device__ float4  g_et[EMAX];
__device__ float4  g_gt[EMAX];            // per-edge mix gates (per head)

// ------------------- helpers -------------------
__device__ __forceinline__ float softplus_f(float v) {
    return (v > 20.0f) ? v : log1pf(__expf(v));
}
__device__ __forceinline__ float sigmoid_f(float v) {
    return 1.0f / (1.0f + __expf(-v));
}
__device__ __forceinline__ float wred_max(float v) {
#pragma unroll
    for (int d = 16; d; d >>= 1) v = fmaxf(v, __shfl_xor_sync(0xffffffffu, v, d));
    return v;
}
__device__ __forceinline__ float wred_sum(float v) {
#pragma unroll
    for (int d = 16; d; d >>= 1) v += __shfl_xor_sync(0xffffffffu, v, d);
    return v;
}

// ------------------- K0: zero counters -------------------
__global__ void k_zero(int n) {
    int i = blockIdx.x * blockDim.x + threadIdx.x;
    if (i < n) g_cnt[i] = 0;
}

// ------------------- K1: score vectors v = W_proj @ score -------------------
__global__ void k_vec(const float* __restrict__ w_proj,
                      const float* __restrict__ rscore,
                      const float* __restrict__ tscore) {
    int tid = threadIdx.x;          // tid = h*64 + f
    int h = tid >> 6;
    const float* wp = w_proj + tid * F;   // w_proj[h][f][:]
    float a = 0.0f, b = 0.0f;
#pragma unroll
    for (int g = 0; g < F; g++) {
        float w = wp[g];
        a += w * rscore[h * F + g];
        b += w * tscore[h * F + g];
    }
    g_vrad[tid] = a;
    g_vtan[tid] = b;
}

// ------------------- K1b: node scalars (fp32) -------------------
__global__ void k_scal(const float* __restrict__ x, int n_nodes) {
    int t = blockIdx.x * blockDim.x + threadIdx.x;
    int n = t >> 2, h = t & 3;
    if (n >= n_nodes) return;
    const float* xr = x + n * F;
    const float* vr = g_vrad + h * F;
    const float* vt = g_vtan + h * F;
    float a = 0.0f, b = 0.0f;
#pragma unroll
    for (int f = 0; f < F; f++) {
        float xv = xr[f];
        a += xv * vr[f];
        b += xv * vt[f];
    }
    g_srad[n * H + h] = a;
    g_stan[n * H + h] = b;
}

// ------------------- K2: projections, R/T split across threads -------------------
// 512 threads: tid = mat*256 + ng*64 + h*16 + gq.  mat selects R vs T matrix;
// ng owns 8 nodes of the block's 32; (h, gq) owns g = gq*4..gq*4+3 of head h.
// One weight matrix streamed per thread as float4 LDG (L1-resident working set),
// x staged in 8 KB smem (broadcast LDS). 32 accum regs -> 2 blocks/SM.
#define NPB 32
__global__ void __launch_bounds__(512, 2) k_proj(const float* __restrict__ x,
                                                 const float* __restrict__ w_radial,
                                                 const float* __restrict__ w_tang,
                                                 int n_nodes) {
    __shared__ float xs[NPB * F];
    int tid = threadIdx.x;
    int mat = tid >> 8;
    int rem = tid & 255;
    int ng = rem >> 6;
    int h  = (rem >> 4) & 3;
    int gq = rem & 15;
    int base = blockIdx.x * NPB;

    for (int i = tid; i < NPB * F; i += 512) {
        int n = base + (i >> 6);
        xs[i] = (n < n_nodes) ? x[n * F + (i & 63)] : 0.0f;
    }
    __syncthreads();

    float4 acc[8];
#pragma unroll
    for (int j = 0; j < 8; j++) acc[j] = make_float4(0.f, 0.f, 0.f, 0.f);

    const float* w = mat ? w_tang : w_radial;
    const float4* w4 = (const float4*)(w + h * F * F) + gq;
    const float*  xb = &xs[ng * 8 * F];

#pragma unroll 2
    for (int f = 0; f < F; f++) {
        float4 wv = __ldg(&w4[f * 16]);
#pragma unroll
        for (int j = 0; j < 8; j++) {
            float xv = xb[j * F + f];
            acc[j].x += xv * wv.x; acc[j].y += xv * wv.y;
            acc[j].z += xv * wv.z; acc[j].w += xv * wv.w;
        }
    }

    __half* dstBase = mat ? g_Th : g_Rh;
#pragma unroll
    for (int j = 0; j < 8; j++) {
        int n = base + ng * 8 + j;
        if (n >= n_nodes) break;
        __half2* d = (__half2*)&dstBase[n * 256];
        int p0 = gq * 2;
        d[p0 * 4 + h]       = __floats2half2_rn(acc[j].x, acc[j].y);
        d[(p0 + 1) * 4 + h] = __floats2half2_rn(acc[j].z, acc[j].w);
    }
}

// ------------------- K3: histogram by receiver -------------------
__global__ void k_hist(const int* __restrict__ ei, int n_edges, int n_nodes) {
    int e = blockIdx.x * blockDim.x + threadIdx.x;
    if (e >= n_edges) return;
    int r = ei[n_edges + e];
    if ((unsigned)r < (unsigned)n_nodes) atomicAdd(&g_cnt[r], 1);
}

// ------------------- K4: single-block exclusive scan -------------------
__global__ void k_scan(int n) {
    __shared__ int part[1024];
    int t = threadIdx.x;
    int chunk = (n + 1023) >> 10;
    int b = t * chunk;
    int e = min(b + chunk, n);
    int s = 0;
    for (int i = b; i < e; i++) s += g_cnt[i];
    part[t] = s;
    __syncthreads();
    for (int d = 1; d < 1024; d <<= 1) {
        int v = (t >= d) ? part[t - d] : 0;
        __syncthreads();
        part[t] += v;
        __syncthreads();
    }
    int run = (t > 0) ? part[t - 1] : 0;
    for (int i = b; i < e; i++) {
        g_off[i] = run;
        g_cur[i] = run;
        run += g_cnt[i];
    }
    if (e == n) g_off[n] = run;
}

// ------------------- K5: scatter edges into CSR order -------------------
__global__ void k_sort(const int* __restrict__ ei,
                       const float* __restrict__ elen,
                       int n_edges, int n_nodes) {
    int e = blockIdx.x * blockDim.x + threadIdx.x;
    if (e >= n_edges) return;
    int s = ei[e], r = ei[n_edges + e];
    if ((unsigned)s >= (unsigned)n_nodes || (unsigned)r >= (unsigned)n_nodes) return;
    int pos = atomicAdd(&g_cur[r], 1);
    g_ss[pos] = s;
    g_sl[pos] = elen[e];
}

// ------------------- K6: per-receiver softmax + aggregate (warp per node) -------------------
__global__ void __launch_bounds__(256) k_main(const float* __restrict__ rdls,
                                              const float* __restrict__ rtb,
                                              const float* __restrict__ rtw,
                                              const float* __restrict__ mixb,
                                              const float* __restrict__ mixs,
                                              int n_nodes) {
    int r = (blockIdx.x * blockDim.x + threadIdx.x) >> 5;
    int lane = threadIdx.x & 31;
    if (r >= n_nodes) return;
    int beg = g_off[r], end = g_off[r + 1];

    float2* aggp = (float2*)g_agg;
    if (beg == end) {
        aggp[r * 32 + lane] = make_float2(0.0f, 0.0f);
        return;
    }

    float dist_scale = softplus_f(rdls[0]);
    float4 tb = *(const float4*)rtb;
    float4 tw = *(const float4*)rtw;
    float4 mb = *(const float4*)mixb;
    float4 ms = *(const float4*)mixs;
    float4 srr = *(const float4*)&g_srad[r * 4];
    float4 str = *(const float4*)&g_stan[r * 4];

    const float NEG = __int_as_float(0xff800000);
    float mr0 = NEG, mr1 = NEG, mr2 = NEG, mr3 = NEG;
    float mt0 = NEG, mt1 = NEG, mt2 = NEG, mt3 = NEG;

    // ---- pass A: per-head max ----
    for (int i = beg + lane; i < end; i += 32) {
        int s = g_ss[i];
        float len = g_sl[i];
        float4 ss = *(const float4*)&g_srad[s * 4];
        float4 ts = *(const float4*)&g_stan[s * 4];
        float c = dist_scale * len;
        float t0 = softplus_f(tb.x + tw.x * len) + 1e-4f;
        float t1 = softplus_f(tb.y + tw.y * len) + 1e-4f;
        float t2 = softplus_f(tb.z + tw.z * len) + 1e-4f;
        float t3 = softplus_f(tb.w + tw.w * len) + 1e-4f;
        mr0 = fmaxf(mr0, (ss.x - srr.x - c) / t0);
        mr1 = fmaxf(mr1, (ss.y - srr.y - c) / t1);
        mr2 = fmaxf(mr2, (ss.z - srr.z - c) / t2);
        mr3 = fmaxf(mr3, (ss.w - srr.w - c) / t3);
        mt0 = fmaxf(mt0, ts.x - str.x);
        mt1 = fmaxf(mt1, ts.y - str.y);
        mt2 = fmaxf(mt2, ts.z - str.z);
        mt3 = fmaxf(mt3, ts.w - str.w);
    }
    mr0 = wred_max(mr0); mr1 = wred_max(mr1); mr2 = wred_max(mr2); mr3 = wred_max(mr3);
    mt0 = wred_max(mt0); mt1 = wred_max(mt1); mt2 = wred_max(mt2); mt3 = wred_max(mt3);

    // ---- pass B: exps + gates + denominators ----
    float dr0 = 0, dr1 = 0, dr2 = 0, dr3 = 0;
    float dt0 = 0, dt1 = 0, dt2 = 0, dt3 = 0;
    for (int i = beg + lane; i < end; i += 32) {
        int s = g_ss[i];
        float len = g_sl[i];
        float4 ss = *(const float4*)&g_srad[s * 4];
        float4 ts = *(const float4*)&g_stan[s * 4];
        float c = dist_scale * len;
        float t0 = softplus_f(tb.x + tw.x * len) + 1e-4f;
        float t1 = softplus_f(tb.y + tw.y * len) + 1e-4f;
        float t2 = softplus_f(tb.z + tw.z * len) + 1e-4f;
        float t3 = softplus_f(tb.w + tw.w * len) + 1e-4f;
        float4 er, et, gt;
        er.x = __expf((ss.x - srr.x - c) / t0 - mr0);
        er.y = __expf((ss.y - srr.y - c) / t1 - mr1);
        er.z = __expf((ss.z - srr.z - c) / t2 - mr2);
        er.w = __expf((ss.w - srr.w - c) / t3 - mr3);
        et.x = __expf(ts.x - str.x - mt0);
        et.y = __expf(ts.y - str.y - mt1);
        et.z = __expf(ts.z - str.z - mt2);
        et.w = __expf(ts.w - str.w - mt3);
        gt.x = sigmoid_f(mb.x + ms.x * len);
        gt.y = sigmoid_f(mb.y + ms.y * len);
        gt.z = sigmoid_f(mb.z + ms.z * len);
        gt.w = sigmoid_f(mb.w + ms.w * len);
        g_er[i] = er;
        g_et[i] = et;
        g_gt[i] = gt;
        dr0 += er.x; dr1 += er.y; dr2 += er.z; dr3 += er.w;
        dt0 += et.x; dt1 += et.y; dt2 += et.z; dt3 += et.w;
    }
    dr0 = wred_sum(dr0); dr1 = wred_sum(dr1); dr2 = wred_sum(dr2); dr3 = wred_sum(dr3);
    dt0 = wred_sum(dt0); dt1 = wred_sum(dt1); dt2 = wred_sum(dt2); dt3 = wred_sum(dt3);
    dr0 = 1.0f / (dr0 + 1e-9f); dr1 = 1.0f / (dr1 + 1e-9f);
    dr2 = 1.0f / (dr2 + 1e-9f); dr3 = 1.0f / (dr3 + 1e-9f);
    dt0 = 1.0f / (dt0 + 1e-9f); dt1 = 1.0f / (dt1 + 1e-9f);
    dt2 = 1.0f / (dt2 + 1e-9f); dt3 = 1.0f / (dt3 + 1e-9f);

    // ---- pass C: inline weights, gather senders, accumulate ----
    // W totals accumulated redundantly in every lane (all lanes see all edges).
    const uint4* Rp = (const uint4*)g_Rh;   // 16B = all 4 heads of one g-pair
    const uint4* Tp = (const uint4*)g_Th;
    float W10 = 0, W11 = 0, W12 = 0, W13 = 0;
    float W20 = 0, W21 = 0, W22 = 0, W23 = 0;
    float ax = 0.0f, ay = 0.0f;
    for (int i = beg; i < end; i++) {
        int s = g_ss[i];
        float4 er = g_er[i];
        float4 et = g_et[i];
        float4 gt = g_gt[i];
        float b0 = gt.x * er.x * dr0 + (1.0f - gt.x) * et.x * dt0;
        float b1 = gt.y * er.y * dr1 + (1.0f - gt.y) * et.y * dt1;
        float b2 = gt.z * er.z * dr2 + (1.0f - gt.z) * et.z * dt2;
        float b3 = gt.w * er.w * dr3 + (1.0f - gt.w) * et.w * dt3;
        float w1x = b0 * gt.x, w2x = b0 * (1.0f - gt.x);
        float w1y = b1 * gt.y, w2y = b1 * (1.0f - gt.y);
        float w1z = b2 * gt.z, w2z = b2 * (1.0f - gt.z);
        float w1w = b3 * gt.w, w2w = b3 * (1.0f - gt.w);
        W10 += w1x; W11 += w1y; W12 += w1z; W13 += w1w;
        W20 += w2x; W21 += w2y; W22 += w2z; W23 += w2w;

        uint4 rv = Rp[s * 32 + lane];
        uint4 tv = Tp[s * 32 + lane];
        const __half2* rh = (const __half2*)&rv;
        const __half2* th = (const __half2*)&tv;
        float2 r0 = __half22float2(rh[0]), r1 = __half22float2(rh[1]);
        float2 r2 = __half22float2(rh[2]), r3 = __half22float2(rh[3]);
        float2 t0 = __half22float2(th[0]), t1 = __half22float2(th[1]);
        float2 t2 = __half22float2(th[2]), t3 = __half22float2(th[3]);
        ax += w1x * r0.x + w2x * t0.x + w1y * r1.x + w2y * t1.x
            + w1z * r2.x + w2z * t2.x + w1w * r3.x + w2w * t3.x;
        ay += w1x * r0.y + w2x * t0.y + w1y * r1.y + w2y * t1.y
            + w1z * r2.y + w2z * t2.y + w1w * r3.y + w2w * t3.y;
    }
    // subtract factored receiver part
    {
        uint4 rv = Rp[r * 32 + lane];
        uint4 tv = Tp[r * 32 + lane];
        const __half2* rh = (const __half2*)&rv;
        const __half2* th = (const __half2*)&tv;
        float2 r0 = __half22float2(rh[0]), r1 = __half22float2(rh[1]);
        float2 r2 = __half22float2(rh[2]), r3 = __half22float2(rh[3]);
        float2 t0 = __half22float2(th[0]), t1 = __half22float2(th[1]);
        float2 t2 = __half22float2(th[2]), t3 = __half22float2(th[3]);
        ax -= W10 * r0.x + W20 * t0.x + W11 * r1.x + W21 * t1.x
            + W12 * r2.x + W22 * t2.x + W13 * r3.x + W23 * t3.x;
        ay -= W10 * r0.y + W20 * t0.y + W11 * r1.y + W21 * t1.y
            + W12 * r2.y + W22 * t2.y + W13 * r3.y + W23 * t3.y;
    }
    aggp[r * 32 + lane] = make_float2(ax * 0.25f, ay * 0.25f);
}

// ------------------- K7: out = x + agg @ w_out -------------------
#define ONB 4
__global__ void k_out(const float* __restrict__ x,
                      const float* __restrict__ w_out,
                      float* __restrict__ out,
                      int n_nodes) {
    __shared__ float sw[F * F];
    __shared__ float ag[ONB * F];
    int tid = threadIdx.x;
    for (int i = tid; i < F * F; i += 256) sw[i] = w_out[i];
    int nl = tid >> 6, g = tid & 63;
    int n = blockIdx.x * ONB + nl;
    if (n < n_nodes) ag[nl * F + g] = g_agg[n * F + g];
    __syncthreads();
    if (n >= n_nodes) return;
    float acc = x[n * F + g];
#pragma unroll
    for (int f = 0; f < F; f++) acc += ag[nl * F + f] * sw[f * F + g];
    out[n * F + g] = acc;
}

// ------------------- launch -------------------
extern "C" void kernel_launch(void* const* d_in, const int* in_sizes, int n_in,
                              void* d_out, int out_size) {
    const float* x     = (const float*)d_in[0];
    const int*   ei    = (const int*)d_in[1];     // edge_index staged as int32, [2, E]
    // d_in[2] = edge_vec (unused by reference)
    const float* elen  = (const float*)d_in[3];
    const float* wprj  = (const float*)d_in[4];
    const float* wrad  = (const float*)d_in[5];
    const float* wtan  = (const float*)d_in[6];
    const float* rsc   = (const float*)d_in[7];
    const float* tsc   = (const float*)d_in[8];
    const float* rdls  = (const float*)d_in[9];
    const float* rtb   = (const float*)d_in[10];
    const float* rtw   = (const float*)d_in[11];
    const float* mixb  = (const float*)d_in[12];
    const float* mixs  = (const float*)d_in[13];
    const float* wout  = (const float*)d_in[14];
    float*       out   = (float*)d_out;

    int n_nodes = in_sizes[0] / F;
    int n_edges = in_sizes[3];

    k_zero<<<(n_nodes + 255) / 256, 256>>>(n_nodes);
    k_vec<<<1, H * F>>>(wprj, rsc, tsc);
    k_scal<<<(n_nodes * H + 255) / 256, 256>>>(x, n_nodes);

    k_proj<<<(n_nodes + NPB - 1) / NPB, 512>>>(x, wrad, wtan, n_nodes);

    k_hist<<<(n_edges + 255) / 256, 256>>>(ei, n_edges, n_nodes);
    k_scan<<<1, 1024>>>(n_nodes);
    k_sort<<<(n_edges + 255) / 256, 256>>>(ei, elen, n_edges, n_nodes);

    k_main<<<(n_nodes * 32 + 255) / 256, 256>>>(rdls, rtb, rtw, mixb, mixs, n_nodes);
    k_out<<<(n_nodes + ONB - 1) / ONB, 256>>>(x, wout, out, n_nodes);
}

// round 8
// speedup vs baseline: 1.0420x; 1.0420x over previous
#include <cuda_runtime.h>
#include <cuda_bf16.h>
#include <cuda_fp16.h>
#include <cstdint>

#define NMAX 20000
#define EMAX 320000
#define F 64
#define H 4

// ------------------- scratch (static device globals; no allocation) -------------------
// fp16 projections, interleaved layout: halves at  n*256 + p*8 + h*2 + k
// (p = g-pair index 0..31, k = element within pair, h = head)
// -> one 16-byte chunk per (n,p) holds all 4 heads of that g-pair.
__device__ __half  g_Rh[NMAX * H * F];
__device__ __half  g_Th[NMAX * H * F];
__device__ float   g_srad[NMAX * H];      // [n][h]
__device__ float   g_stan[NMAX * H];
__device__ float   g_agg[NMAX * F];       // head-averaged aggregate
__device__ float   g_vrad[H * F];         // w_proj @ radial_score
__device__ float   g_vtan[H * F];

// CSR sort scratch
__device__ int     g_cnt[NMAX];
__device__ int     g_off[NMAX + 1];
__device__ int     g_cur[NMAX];
__device__ int     g_ss[EMAX];            // sorted sender
__device__ float   g_sl[EMAX];            // sorted edge_len
__device__ float4  g_er[EMAX];            // exp(rad logit - max) per head
__device__ float4  g_et[EMAX];
__device__ float4  g_w1[EMAX];            // per-edge blended weights
__device__ float4  g_w2[EMAX];

// ------------------- helpers -------------------
__device__ __forceinline__ float softplus_f(float v) {
    return (v > 20.0f) ? v : log1pf(__expf(v));
}
__device__ __forceinline__ float sigmoid_f(float v) {
    return 1.0f / (1.0f + __expf(-v));
}
__device__ __forceinline__ float wred_max(float v) {
#pragma unroll
    for (int d = 16; d; d >>= 1) v = fmaxf(v, __shfl_xor_sync(0xffffffffu, v, d));
    return v;
}
__device__ __forceinline__ float wred_sum(float v) {
#pragma unroll
    for (int d = 16; d; d >>= 1) v += __shfl_xor_sync(0xffffffffu, v, d);
    return v;
}

// ------------------- K0: zero counters -------------------
__global__ void k_zero(int n) {
    int i = blockIdx.x * blockDim.x + threadIdx.x;
    if (i < n) g_cnt[i] = 0;
}

// ------------------- K1: score vectors v = W_proj @ score -------------------
__global__ void k_vec(const float* __restrict__ w_proj,
                      const float* __restrict__ rscore,
                      const float* __restrict__ tscore) {
    int tid = threadIdx.x;          // tid = h*64 + f
    int h = tid >> 6;
    const float* wp = w_proj + tid * F;   // w_proj[h][f][:]
    float a = 0.0f, b = 0.0f;
#pragma unroll
    for (int g = 0; g < F; g++) {
        float w = wp[g];
        a += w * rscore[h * F + g];
        b += w * tscore[h * F + g];
    }
    g_vrad[tid] = a;
    g_vtan[tid] = b;
}

// ------------------- K1b: node scalars (fp32) -------------------
__global__ void k_scal(const float* __restrict__ x, int n_nodes) {
    int t = blockIdx.x * blockDim.x + threadIdx.x;
    int n = t >> 2, h = t & 3;
    if (n >= n_nodes) return;
    const float* xr = x + n * F;
    const float* vr = g_vrad + h * F;
    const float* vt = g_vtan + h * F;
    float a = 0.0f, b = 0.0f;
#pragma unroll
    for (int f = 0; f < F; f++) {
        float xv = xr[f];
        a += xv * vr[f];
        b += xv * vt[f];
    }
    g_srad[n * H + h] = a;
    g_stan[n * H + h] = b;
}

// ------------------- K2: projections, R/T split across threads -------------------
// 512 threads: tid = mat*256 + ng*64 + h*16 + gq.  mat selects R vs T matrix;
// ng owns 8 nodes of the block's 32; (h, gq) owns g = gq*4..gq*4+3 of head h.
// f-loop in chunks of 4: 4x LDG.128 weights (MLP=4) + broadcast LDS.128 x.
#define NPB 32
__global__ void __launch_bounds__(512, 2) k_proj(const float* __restrict__ x,
                                                 const float* __restrict__ w_radial,
                                                 const float* __restrict__ w_tang,
                                                 int n_nodes) {
    __shared__ float xs[NPB * F];
    int tid = threadIdx.x;
    int mat = tid >> 8;
    int rem = tid & 255;
    int ng = rem >> 6;
    int h  = (rem >> 4) & 3;
    int gq = rem & 15;
    int base = blockIdx.x * NPB;

    for (int i = tid; i < NPB * F; i += 512) {
        int n = base + (i >> 6);
        xs[i] = (n < n_nodes) ? x[n * F + (i & 63)] : 0.0f;
    }
    __syncthreads();

    float4 acc[8];
#pragma unroll
    for (int j = 0; j < 8; j++) acc[j] = make_float4(0.f, 0.f, 0.f, 0.f);

    const float* w = mat ? w_tang : w_radial;
    const float4* w4 = (const float4*)(w + h * F * F) + gq;
    const float*  xb = &xs[ng * 8 * F];

    for (int fc = 0; fc < F; fc += 4) {
        float4 wv0 = __ldg(&w4[(fc + 0) * 16]);
        float4 wv1 = __ldg(&w4[(fc + 1) * 16]);
        float4 wv2 = __ldg(&w4[(fc + 2) * 16]);
        float4 wv3 = __ldg(&w4[(fc + 3) * 16]);
#pragma unroll
        for (int j = 0; j < 8; j++) {
            float4 xv = *(const float4*)&xb[j * F + fc];
            acc[j].x += xv.x * wv0.x + xv.y * wv1.x + xv.z * wv2.x + xv.w * wv3.x;
            acc[j].y += xv.x * wv0.y + xv.y * wv1.y + xv.z * wv2.y + xv.w * wv3.y;
            acc[j].z += xv.x * wv0.z + xv.y * wv1.z + xv.z * wv2.z + xv.w * wv3.z;
            acc[j].w += xv.x * wv0.w + xv.y * wv1.w + xv.z * wv2.w + xv.w * wv3.w;
        }
    }

    __half* dstBase = mat ? g_Th : g_Rh;
#pragma unroll
    for (int j = 0; j < 8; j++) {
        int n = base + ng * 8 + j;
        if (n >= n_nodes) break;
        __half2* d = (__half2*)&dstBase[n * 256];
        int p0 = gq * 2;
        d[p0 * 4 + h]       = __floats2half2_rn(acc[j].x, acc[j].y);
        d[(p0 + 1) * 4 + h] = __floats2half2_rn(acc[j].z, acc[j].w);
    }
}

// ------------------- K3: histogram by receiver -------------------
__global__ void k_hist(const int* __restrict__ ei, int n_edges, int n_nodes) {
    int e = blockIdx.x * blockDim.x + threadIdx.x;
    if (e >= n_edges) return;
    int r = ei[n_edges + e];
    if ((unsigned)r < (unsigned)n_nodes) atomicAdd(&g_cnt[r], 1);
}

// ------------------- K4: single-block exclusive scan -------------------
__global__ void k_scan(int n) {
    __shared__ int part[1024];
    int t = threadIdx.x;
    int chunk = (n + 1023) >> 10;
    int b = t * chunk;
    int e = min(b + chunk, n);
    int s = 0;
    for (int i = b; i < e; i++) s += g_cnt[i];
    part[t] = s;
    __syncthreads();
    for (int d = 1; d < 1024; d <<= 1) {
        int v = (t >= d) ? part[t - d] : 0;
        __syncthreads();
        part[t] += v;
        __syncthreads();
    }
    int run = (t > 0) ? part[t - 1] : 0;
    for (int i = b; i < e; i++) {
        g_off[i] = run;
        g_cur[i] = run;
        run += g_cnt[i];
    }
    if (e == n) g_off[n] = run;
}

// ------------------- K5: scatter edges into CSR order -------------------
__global__ void k_sort(const int* __restrict__ ei,
                       const float* __restrict__ elen,
                       int n_edges, int n_nodes) {
    int e = blockIdx.x * blockDim.x + threadIdx.x;
    if (e >= n_edges) return;
    int s = ei[e], r = ei[n_edges + e];
    if ((unsigned)s >= (unsigned)n_nodes || (unsigned)r >= (unsigned)n_nodes) return;
    int pos = atomicAdd(&g_cur[r], 1);
    g_ss[pos] = s;
    g_sl[pos] = elen[e];
}

// ------------------- K6: per-receiver softmax + aggregate (warp per node) -------------------
__global__ void __launch_bounds__(256) k_main(const float* __restrict__ rdls,
                                              const float* __restrict__ rtb,
                                              const float* __restrict__ rtw,
                                              const float* __restrict__ mixb,
                                              const float* __restrict__ mixs,
                                              int n_nodes) {
    int r = (blockIdx.x * blockDim.x + threadIdx.x) >> 5;
    int lane = threadIdx.x & 31;
    if (r >= n_nodes) return;
    int beg = g_off[r], end = g_off[r + 1];

    float2* aggp = (float2*)g_agg;
    if (beg == end) {
        aggp[r * 32 + lane] = make_float2(0.0f, 0.0f);
        return;
    }

    float dist_scale = softplus_f(rdls[0]);
    float4 tb = *(const float4*)rtb;
    float4 tw = *(const float4*)rtw;
    float4 mb = *(const float4*)mixb;
    float4 ms = *(const float4*)mixs;
    float4 srr = *(const float4*)&g_srad[r * 4];
    float4 str = *(const float4*)&g_stan[r * 4];

    const float NEG = __int_as_float(0xff800000);
    float mr0 = NEG, mr1 = NEG, mr2 = NEG, mr3 = NEG;
    float mt0 = NEG, mt1 = NEG, mt2 = NEG, mt3 = NEG;

    // ---- pass A: per-head max ----
    for (int i = beg + lane; i < end; i += 32) {
        int s = g_ss[i];
        float len = g_sl[i];
        float4 ss = *(const float4*)&g_srad[s * 4];
        float4 ts = *(const float4*)&g_stan[s * 4];
        float c = dist_scale * len;
        float t0 = softplus_f(tb.x + tw.x * len) + 1e-4f;
        float t1 = softplus_f(tb.y + tw.y * len) + 1e-4f;
        float t2 = softplus_f(tb.z + tw.z * len) + 1e-4f;
        float t3 = softplus_f(tb.w + tw.w * len) + 1e-4f;
        mr0 = fmaxf(mr0, (ss.x - srr.x - c) / t0);
        mr1 = fmaxf(mr1, (ss.y - srr.y - c) / t1);
        mr2 = fmaxf(mr2, (ss.z - srr.z - c) / t2);
        mr3 = fmaxf(mr3, (ss.w - srr.w - c) / t3);
        mt0 = fmaxf(mt0, ts.x - str.x);
        mt1 = fmaxf(mt1, ts.y - str.y);
        mt2 = fmaxf(mt2, ts.z - str.z);
        mt3 = fmaxf(mt3, ts.w - str.w);
    }
    mr0 = wred_max(mr0); mr1 = wred_max(mr1); mr2 = wred_max(mr2); mr3 = wred_max(mr3);
    mt0 = wred_max(mt0); mt1 = wred_max(mt1); mt2 = wred_max(mt2); mt3 = wred_max(mt3);

    // ---- pass B: exps + denominators ----
    float dr0 = 0, dr1 = 0, dr2 = 0, dr3 = 0;
    float dt0 = 0, dt1 = 0, dt2 = 0, dt3 = 0;
    for (int i = beg + lane; i < end; i += 32) {
        int s = g_ss[i];
        float len = g_sl[i];
        float4 ss = *(const float4*)&g_srad[s * 4];
        float4 ts = *(const float4*)&g_stan[s * 4];
        float c = dist_scale * len;
        float t0 = softplus_f(tb.x + tw.x * len) + 1e-4f;
        float t1 = softplus_f(tb.y + tw.y * len) + 1e-4f;
        float t2 = softplus_f(tb.z + tw.z * len) + 1e-4f;
        float t3 = softplus_f(tb.w + tw.w * len) + 1e-4f;
        float4 er, et;
        er.x = __expf((ss.x - srr.x - c) / t0 - mr0);
        er.y = __expf((ss.y - srr.y - c) / t1 - mr1);
        er.z = __expf((ss.z - srr.z - c) / t2 - mr2);
        er.w = __expf((ss.w - srr.w - c) / t3 - mr3);
        et.x = __expf(ts.x - str.x - mt0);
        et.y = __expf(ts.y - str.y - mt1);
        et.z = __expf(ts.z - str.z - mt2);
        et.w = __expf(ts.w - str.w - mt3);
        g_er[i] = er;
        g_et[i] = et;
        dr0 += er.x; dr1 += er.y; dr2 += er.z; dr3 += er.w;
        dt0 += et.x; dt1 += et.y; dt2 += et.z; dt3 += et.w;
    }
    dr0 = wred_sum(dr0); dr1 = wred_sum(dr1); dr2 = wred_sum(dr2); dr3 = wred_sum(dr3);
    dt0 = wred_sum(dt0); dt1 = wred_sum(dt1); dt2 = wred_sum(dt2); dt3 = wred_sum(dt3);
    dr0 = 1.0f / (dr0 + 1e-9f); dr1 = 1.0f / (dr1 + 1e-9f);
    dr2 = 1.0f / (dr2 + 1e-9f); dr3 = 1.0f / (dr3 + 1e-9f);
    dt0 = 1.0f / (dt0 + 1e-9f); dt1 = 1.0f / (dt1 + 1e-9f);
    dt2 = 1.0f / (dt2 + 1e-9f); dt3 = 1.0f / (dt3 + 1e-9f);

    // ---- pass B2: per-edge blended weights + receiver-side totals (lane-parallel) ----
    float W10 = 0, W11 = 0, W12 = 0, W13 = 0;
    float W20 = 0, W21 = 0, W22 = 0, W23 = 0;
    for (int i = beg + lane; i < end; i += 32) {
        float len = g_sl[i];
        float4 er = g_er[i];
        float4 et = g_et[i];
        float g0 = sigmoid_f(mb.x + ms.x * len);
        float g1 = sigmoid_f(mb.y + ms.y * len);
        float g2 = sigmoid_f(mb.z + ms.z * len);
        float g3 = sigmoid_f(mb.w + ms.w * len);
        float b0 = g0 * er.x * dr0 + (1.0f - g0) * et.x * dt0;
        float b1 = g1 * er.y * dr1 + (1.0f - g1) * et.y * dt1;
        float b2 = g2 * er.z * dr2 + (1.0f - g2) * et.z * dt2;
        float b3 = g3 * er.w * dr3 + (1.0f - g3) * et.w * dt3;
        float4 w1, w2;
        w1.x = b0 * g0; w2.x = b0 * (1.0f - g0);
        w1.y = b1 * g1; w2.y = b1 * (1.0f - g1);
        w1.z = b2 * g2; w2.z = b2 * (1.0f - g2);
        w1.w = b3 * g3; w2.w = b3 * (1.0f - g3);
        g_w1[i] = w1;
        g_w2[i] = w2;
        W10 += w1.x; W11 += w1.y; W12 += w1.z; W13 += w1.w;
        W20 += w2.x; W21 += w2.y; W22 += w2.z; W23 += w2.w;
    }
    W10 = wred_sum(W10); W11 = wred_sum(W11); W12 = wred_sum(W12); W13 = wred_sum(W13);
    W20 = wred_sum(W20); W21 = wred_sum(W21); W22 = wred_sum(W22); W23 = wred_sum(W23);

    // ---- pass C: gather senders (one LDG.128 per matrix), accumulate ----
    const uint4* Rp = (const uint4*)g_Rh;   // 16B = all 4 heads of one g-pair
    const uint4* Tp = (const uint4*)g_Th;
    float ax = 0.0f, ay = 0.0f;
    for (int i = beg; i < end; i++) {
        int s = g_ss[i];
        float4 w1 = g_w1[i];
        float4 w2 = g_w2[i];
        uint4 rv = Rp[s * 32 + lane];
        uint4 tv = Tp[s * 32 + lane];
        const __half2* rh = (const __half2*)&rv;
        const __half2* th = (const __half2*)&tv;
        float2 r0 = __half22float2(rh[0]), r1 = __half22float2(rh[1]);
        float2 r2 = __half22float2(rh[2]), r3 = __half22float2(rh[3]);
        float2 t0 = __half22float2(th[0]), t1 = __half22float2(th[1]);
        float2 t2 = __half22float2(th[2]), t3 = __half22float2(th[3]);
        ax += w1.x * r0.x + w2.x * t0.x + w1.y * r1.x + w2.y * t1.x
            + w1.z * r2.x + w2.z * t2.x + w1.w * r3.x + w2.w * t3.x;
        ay += w1.x * r0.y + w2.x * t0.y + w1.y * r1.y + w2.y * t1.y
            + w1.z * r2.y + w2.z * t2.y + w1.w * r3.y + w2.w * t3.y;
    }
    // subtract factored receiver part
    {
        uint4 rv = Rp[r * 32 + lane];
        uint4 tv = Tp[r * 32 + lane];
        const __half2* rh = (const __half2*)&rv;
        const __half2* th = (const __half2*)&tv;
        float2 r0 = __half22float2(rh[0]), r1 = __half22float2(rh[1]);
        float2 r2 = __half22float2(rh[2]), r3 = __half22float2(rh[3]);
        float2 t0 = __half22float2(th[0]), t1 = __half22float2(th[1]);
        float2 t2 = __half22float2(th[2]), t3 = __half22float2(th[3]);
        ax -= W10 * r0.x + W20 * t0.x + W11 * r1.x + W21 * t1.x
            + W12 * r2.x + W22 * t2.x + W13 * r3.x + W23 * t3.x;
        ay -= W10 * r0.y + W20 * t0.y + W11 * r1.y + W21 * t1.y
            + W12 * r2.y + W22 * t2.y + W13 * r3.y + W23 * t3.y;
    }
    aggp[r * 32 + lane] = make_float2(ax * 0.25f, ay * 0.25f);
}

// ------------------- K7: out = x + agg @ w_out -------------------
#define ONB 4
__global__ void k_out(const float* __restrict__ x,
                      const float* __restrict__ w_out,
                      float* __restrict__ out,
                      int n_nodes) {
    __shared__ float sw[F * F];
    __shared__ float ag[ONB * F];
    int tid = threadIdx.x;
    for (int i = tid; i < F * F; i += 256) sw[i] = w_out[i];
    int nl = tid >> 6, g = tid & 63;
    int n = blockIdx.x * ONB + nl;
    if (n < n_nodes) ag[nl * F + g] = g_agg[n * F + g];
    __syncthreads();
    if (n >= n_nodes) return;
    float acc = x[n * F + g];
#pragma unroll
    for (int f = 0; f < F; f++) acc += ag[nl * F + f] * sw[f * F + g];
    out[n * F + g] = acc;
}

// ------------------- launch -------------------
extern "C" void kernel_launch(void* const* d_in, const int* in_sizes, int n_in,
                              void* d_out, int out_size) {
    const float* x     = (const float*)d_in[0];
    const int*   ei    = (const int*)d_in[1];     // edge_index staged as int32, [2, E]
    // d_in[2] = edge_vec (unused by reference)
    const float* elen  = (const float*)d_in[3];
    const float* wprj  = (const float*)d_in[4];
    const float* wrad  = (const float*)d_in[5];
    const float* wtan  = (const float*)d_in[6];
    const float* rsc   = (const float*)d_in[7];
    const float* tsc   = (const float*)d_in[8];
    const float* rdls  = (const float*)d_in[9];
    const float* rtb   = (const float*)d_in[10];
    const float* rtw   = (const float*)d_in[11];
    const float* mixb  = (const float*)d_in[12];
    const float* mixs  = (const float*)d_in[13];
    const float* wout  = (const float*)d_in[14];
    float*       out   = (float*)d_out;

    int n_nodes = in_sizes[0] / F;
    int n_edges = in_sizes[3];

    k_zero<<<(n_nodes + 255) / 256, 256>>>(n_nodes);
    k_vec<<<1, H * F>>>(wprj, rsc, tsc);
    k_scal<<<(n_nodes * H + 255) / 256, 256>>>(x, n_nodes);

    k_proj<<<(n_nodes + NPB - 1) / NPB, 512>>>(x, wrad, wtan, n_nodes);

    k_hist<<<(n_edges + 255) / 256, 256>>>(ei, n_edges, n_nodes);
    k_scan<<<1, 1024>>>(n_nodes);
    k_sort<<<(n_edges + 255) / 256, 256>>>(ei, elen, n_edges, n_nodes);

    k_main<<<(n_nodes * 32 + 255) / 256, 256>>>(rdls, rtb, rtw, mixb, mixs, n_nodes);
    k_out<<<(n_nodes + ONB - 1) / ONB, 256>>>(x, wout, out, n_nodes);
}